// round 12
// baseline (speedup 1.0000x reference)
#include <cuda_runtime.h>
#include <cuda_fp16.h>
#include <cstdint>

// AdaLoRALinear: out[8192,4096] = x[8192,4096] @ (W + (B*sigma_m)@A)^T
// Single-pass fp16 GEMM on mma.sync (at the legacy-HMMA issue ceiling).
// This round: fold does 2 o-rows/block (halves A L2 re-reads, keeps high
// block count); streaming loads for the read-once fp32 inputs.

#define D_DIM 4096
#define R_DIM 16
#define M_DIM 8192
#define SCALING 1.0f
#define THRESH  0.01f

#define BM 128
#define BN 128
#define BK 64                  // 64 fp16 = 128B row (SW128 atom)
#define KITERS (D_DIM / BK)    // 64

__device__ __half g_x16[(size_t)M_DIM * D_DIM];
__device__ __half g_w16[(size_t)D_DIM * D_DIM];

// ---------------------------------------------------------------------------
// helpers
// ---------------------------------------------------------------------------
__device__ __forceinline__ uint32_t smem_u32(const void* p) {
    uint32_t a;
    asm("{ .reg .u64 t; cvta.to.shared.u64 t, %1; cvt.u32.u64 %0, t; }"
        : "=r"(a) : "l"(p));
    return a;
}
__device__ __forceinline__ uint32_t swz128(uint32_t off) {
    return off ^ ((off >> 3) & 0x70);
}
__device__ __forceinline__ void cp16(uint32_t smem, const void* g) {
    asm volatile("cp.async.cg.shared.global [%0], [%1], 16;\n"
                 :: "r"(smem), "l"(g) : "memory");
}
__device__ __forceinline__ void cp_commit() {
    asm volatile("cp.async.commit_group;\n" ::: "memory");
}
__device__ __forceinline__ void cp_wait1() {
    asm volatile("cp.async.wait_group 1;\n" ::: "memory");
}
__device__ __forceinline__ void ldsm4(uint32_t* r, uint32_t addr) {
    asm volatile("ldmatrix.sync.aligned.m8n8.x4.shared.b16 {%0,%1,%2,%3}, [%4];"
                 : "=r"(r[0]), "=r"(r[1]), "=r"(r[2]), "=r"(r[3]) : "r"(addr));
}
__device__ __forceinline__ void mma_f16(float* d, const uint32_t* a,
                                        const uint32_t* b) {
    asm volatile(
        "mma.sync.aligned.m16n8k16.row.col.f32.f16.f16.f32 "
        "{%0,%1,%2,%3}, {%4,%5,%6,%7}, {%8,%9}, {%0,%1,%2,%3};"
        : "+f"(d[0]), "+f"(d[1]), "+f"(d[2]), "+f"(d[3])
        : "r"(a[0]), "r"(a[1]), "r"(a[2]), "r"(a[3]), "r"(b[0]), "r"(b[1]));
}
__device__ __forceinline__ float4 ldcs4(const float* p) {
    float4 v;
    asm volatile("ld.global.cs.v4.f32 {%0,%1,%2,%3}, [%4];"
                 : "=f"(v.x), "=f"(v.y), "=f"(v.z), "=f"(v.w) : "l"(p));
    return v;
}

// ---------------------------------------------------------------------------
// Merged prep.
// Fold blocks [0, FOLD_BLOCKS): 1024-col i-slice x 2 o-rows; A slice loaded
//   once to registers (16 float4), reused for both rows. W via streaming ld.
// Conv blocks [FOLD_BLOCKS, +CONV_BLOCKS): x -> fp16, 8 elems/thread.
// ---------------------------------------------------------------------------
#define FOLD_BLOCKS 8192       // 4 i-slices x 2048 o-pairs
#define CONV_BLOCKS 16384      // M*D / 8 / 256

__global__ void prep_kernel(const float* __restrict__ x,
                            const float* __restrict__ W,
                            const float* __restrict__ A,
                            const float* __restrict__ B,
                            const float* __restrict__ sigma) {
    const int bid = blockIdx.x;
    if (bid < FOLD_BLOCKS) {
        __shared__ float bsig[2][16];
        const int slice = bid & 3;
        const int o0 = (bid >> 2) * 2;
        const int i = slice * 1024 + threadIdx.x * 4;

        if (threadIdx.x < 32) {
            const int oo = threadIdx.x >> 4;
            const int r  = threadIdx.x & 15;
            float s = sigma[r];
            s = (fabsf(s) >= THRESH) ? s : 0.0f;
            bsig[oo][r] = B[(o0 + oo) * R_DIM + r] * s * SCALING;
        }
        __syncthreads();

        float4 a[R_DIM];
#pragma unroll
        for (int r = 0; r < R_DIM; r++)
            a[r] = *reinterpret_cast<const float4*>(A + (size_t)r * D_DIM + i);

#pragma unroll
        for (int oo = 0; oo < 2; oo++) {
            const size_t idx = (size_t)(o0 + oo) * D_DIM + i;
            const float4 w4 = ldcs4(W + idx);       // read-once: evict-first
            float acc[4] = {w4.x, w4.y, w4.z, w4.w};
#pragma unroll
            for (int r = 0; r < R_DIM; r++) {
                const float b = bsig[oo][r];
                acc[0] = fmaf(b, a[r].x, acc[0]);
                acc[1] = fmaf(b, a[r].y, acc[1]);
                acc[2] = fmaf(b, a[r].z, acc[2]);
                acc[3] = fmaf(b, a[r].w, acc[3]);
            }
            __half h[4];
#pragma unroll
            for (int j = 0; j < 4; j++) h[j] = __float2half_rn(acc[j]);
            *reinterpret_cast<uint2*>(&g_w16[idx]) =
                *reinterpret_cast<uint2*>(h);
        }
    } else {
        const size_t t = (size_t)(bid - FOLD_BLOCKS) * 256 + threadIdx.x;
        const float4 v0 = ldcs4(x + t * 8);         // read-once: evict-first
        const float4 v1 = ldcs4(x + t * 8 + 4);
        __half h[8] = {__float2half_rn(v0.x), __float2half_rn(v0.y),
                       __float2half_rn(v0.z), __float2half_rn(v0.w),
                       __float2half_rn(v1.x), __float2half_rn(v1.y),
                       __float2half_rn(v1.z), __float2half_rn(v1.w)};
        *reinterpret_cast<uint4*>(&g_x16[t * 8]) =
            *reinterpret_cast<uint4*>(h);
    }
}

// ---------------------------------------------------------------------------
// GEMM: CTA 128x128, 256 threads, 8 warps (4m x 2n) of 32x64, BK=64,
// 3-stage pipeline (32 KB/stage) -> 96 KB/CTA -> 2 CTAs/SM, 16 warps/SM.
// (Unchanged from round 10 — measured at the HMMA issue ceiling.)
// ---------------------------------------------------------------------------
#define STAGE_BYTES 32768
#define OFF_A 0
#define OFF_B 16384
#define SMEM_BYTES (3 * STAGE_BYTES + 128)

__device__ __forceinline__ void load_stage(uint32_t base, size_t mBase,
                                           size_t nBase, int kt, int tid) {
#pragma unroll
    for (int i = 0; i < 4; i++) {   // A: 128 rows x 8 units = 1024 / 256 thr
        const int u = tid + 256 * i;
        const int row = u >> 3, kc = u & 7;
        const uint32_t so = swz128(row * 128 + kc * 16);
        cp16(base + OFF_A + so, g_x16 + ((mBase + row) << 12) + kt + kc * 8);
    }
#pragma unroll
    for (int i = 0; i < 4; i++) {   // B: 128 rows x 8 units
        const int u = tid + 256 * i;
        const int row = u >> 3, kc = u & 7;
        const uint32_t so = swz128(row * 128 + kc * 16);
        cp16(base + OFF_B + so, g_w16 + ((nBase + row) << 12) + kt + kc * 8);
    }
}

__global__ __launch_bounds__(256, 2)
void gemm_mma_kernel(float* __restrict__ out) {
    extern __shared__ char smem_raw[];
    const uint32_t tiles = (smem_u32(smem_raw) + 127u) & ~127u;

    const int tid = threadIdx.x;
    const int lane = tid & 31;
    const int w = tid >> 5;
    const int wm = w >> 1;        // 0..3 -> M quarter (32 rows)
    const int wn = w & 1;         // 0..1 -> N half (64 cols)
    const size_t mBase = (size_t)blockIdx.y * BM;
    const size_t nBase = (size_t)blockIdx.x * BN;

    float d[2][8][4];
#pragma unroll
    for (int i = 0; i < 2; i++)
#pragma unroll
        for (int j = 0; j < 8; j++)
#pragma unroll
            for (int k = 0; k < 4; k++) d[i][j][k] = 0.0f;

    const int arow = wm * 32 + (lane & 15);
    const int acol = (lane >> 4);
    const int brow = wn * 64 + (lane & 7) + ((lane >> 4) << 3);
    const int bcol = ((lane >> 3) & 1);

    load_stage(tiles, mBase, nBase, 0, tid);
    cp_commit();
    load_stage(tiles + STAGE_BYTES, mBase, nBase, BK, tid);
    cp_commit();

    for (int it = 0; it < KITERS; it++) {
        const uint32_t stg = tiles + (it % 3) * STAGE_BYTES;

        cp_wait1();          // oldest pending group (stage it) complete
        __syncthreads();

        // Issue next loads first: stage (it+2)%3 == (it-1)%3 is drained —
        // every warp passed this barrier, so all finished computing it-1.
        if (it + 2 < KITERS)
            load_stage(tiles + ((it + 2) % 3) * STAGE_BYTES,
                       mBase, nBase, (it + 2) * BK, tid);
        cp_commit();         // empty groups at tail keep wait counts valid

#pragma unroll
        for (int k16 = 0; k16 < 4; k16++) {
            uint32_t a[2][4], b[8][2];
#pragma unroll
            for (int mi = 0; mi < 2; mi++) {
                const uint32_t off =
                    swz128((arow + mi * 16) * 128 + (acol + k16 * 2) * 16);
                ldsm4(a[mi], stg + OFF_A + off);
            }
#pragma unroll
            for (int j = 0; j < 4; j++) {
                uint32_t q[4];
                const uint32_t off =
                    swz128((brow + j * 16) * 128 + (bcol + k16 * 2) * 16);
                ldsm4(q, stg + OFF_B + off);
                b[2 * j][0] = q[0]; b[2 * j][1] = q[1];
                b[2 * j + 1][0] = q[2]; b[2 * j + 1][1] = q[3];
            }
#pragma unroll
            for (int mi = 0; mi < 2; mi++)
#pragma unroll
                for (int nj = 0; nj < 8; nj++)
                    mma_f16(d[mi][nj], a[mi], b[nj]);
        }
    }

#pragma unroll
    for (int mi = 0; mi < 2; mi++) {
        const size_t grow = mBase + wm * 32 + mi * 16 + (lane >> 2);
#pragma unroll
        for (int nj = 0; nj < 8; nj++) {
            const size_t gcol = nBase + wn * 64 + nj * 8 + (lane & 3) * 2;
            *reinterpret_cast<float2*>(out + grow * D_DIM + gcol) =
                make_float2(d[mi][nj][0], d[mi][nj][1]);
            *reinterpret_cast<float2*>(out + (grow + 8) * D_DIM + gcol) =
                make_float2(d[mi][nj][2], d[mi][nj][3]);
        }
    }
}

// ---------------------------------------------------------------------------
// Launch
// ---------------------------------------------------------------------------
extern "C" void kernel_launch(void* const* d_in, const int* in_sizes, int n_in,
                              void* d_out, int out_size) {
    const float* x     = (const float*)d_in[0];
    const float* W     = (const float*)d_in[1];
    const float* lA    = (const float*)d_in[2];
    const float* lB    = (const float*)d_in[3];
    const float* sigma = (const float*)d_in[4];
    float* out = (float*)d_out;
    (void)in_sizes; (void)n_in; (void)out_size;

    prep_kernel<<<FOLD_BLOCKS + CONV_BLOCKS, 256>>>(x, W, lA, lB, sigma);

    cudaFuncSetAttribute(gemm_mma_kernel,
                         cudaFuncAttributeMaxDynamicSharedMemorySize, SMEM_BYTES);
    dim3 gG(D_DIM / BN, M_DIM / BM);
    gemm_mma_kernel<<<gG, 256, SMEM_BYTES>>>(out);
}

// round 13
// speedup vs baseline: 1.0388x; 1.0388x over previous
#include <cuda_runtime.h>
#include <cuda_fp16.h>
#include <cstdint>

// AdaLoRALinear: out[8192,4096] = x[8192,4096] @ (W + (B*sigma_m)@A)^T
// Single-pass fp16 GEMM on mma.sync (at the legacy-HMMA issue ceiling).
// Prep = round-10 shape (best measured), fold/conv blocks parity-interleaved
// so the L1-bound fold overlaps the DRAM-bound x-convert across all SMs.

#define D_DIM 4096
#define R_DIM 16
#define M_DIM 8192
#define SCALING 1.0f
#define THRESH  0.01f

#define BM 128
#define BN 128
#define BK 64                  // 64 fp16 = 128B row (SW128 atom)
#define KITERS (D_DIM / BK)    // 64

__device__ __half g_x16[(size_t)M_DIM * D_DIM];
__device__ __half g_w16[(size_t)D_DIM * D_DIM];

// ---------------------------------------------------------------------------
// helpers
// ---------------------------------------------------------------------------
__device__ __forceinline__ uint32_t smem_u32(const void* p) {
    uint32_t a;
    asm("{ .reg .u64 t; cvta.to.shared.u64 t, %1; cvt.u32.u64 %0, t; }"
        : "=r"(a) : "l"(p));
    return a;
}
__device__ __forceinline__ uint32_t swz128(uint32_t off) {
    return off ^ ((off >> 3) & 0x70);
}
__device__ __forceinline__ void cp16(uint32_t smem, const void* g) {
    asm volatile("cp.async.cg.shared.global [%0], [%1], 16;\n"
                 :: "r"(smem), "l"(g) : "memory");
}
__device__ __forceinline__ void cp_commit() {
    asm volatile("cp.async.commit_group;\n" ::: "memory");
}
__device__ __forceinline__ void cp_wait1() {
    asm volatile("cp.async.wait_group 1;\n" ::: "memory");
}
__device__ __forceinline__ void ldsm4(uint32_t* r, uint32_t addr) {
    asm volatile("ldmatrix.sync.aligned.m8n8.x4.shared.b16 {%0,%1,%2,%3}, [%4];"
                 : "=r"(r[0]), "=r"(r[1]), "=r"(r[2]), "=r"(r[3]) : "r"(addr));
}
__device__ __forceinline__ void mma_f16(float* d, const uint32_t* a,
                                        const uint32_t* b) {
    asm volatile(
        "mma.sync.aligned.m16n8k16.row.col.f32.f16.f16.f32 "
        "{%0,%1,%2,%3}, {%4,%5,%6,%7}, {%8,%9}, {%0,%1,%2,%3};"
        : "+f"(d[0]), "+f"(d[1]), "+f"(d[2]), "+f"(d[3])
        : "r"(a[0]), "r"(a[1]), "r"(a[2]), "r"(a[3]), "r"(b[0]), "r"(b[1]));
}

// ---------------------------------------------------------------------------
// Merged prep, parity-interleaved:
//   even blocks: fold W' -> fp16 (one o-row slice, 4 elems/thread)
//   odd  blocks: convert x -> fp16 (8 elems/thread)
// 16384 fold + 16384 conv = 32768 blocks total.
// ---------------------------------------------------------------------------
#define PREP_BLOCKS 32768

__global__ void prep_kernel(const float* __restrict__ x,
                            const float* __restrict__ W,
                            const float* __restrict__ A,
                            const float* __restrict__ B,
                            const float* __restrict__ sigma) {
    const int bid = blockIdx.x;
    if ((bid & 1) == 0) {
        const int fb = bid >> 1;                 // 0..16383
        __shared__ float bsig[R_DIM];
        const int o = fb >> 2;                   // 0..4095
        const int i = ((fb & 3) * 256 + threadIdx.x) * 4;
        if (threadIdx.x < R_DIM) {
            float s = sigma[threadIdx.x];
            s = (fabsf(s) >= THRESH) ? s : 0.0f;
            bsig[threadIdx.x] = B[o * R_DIM + threadIdx.x] * s * SCALING;
        }
        __syncthreads();

        const size_t idx = (size_t)o * D_DIM + i;
        float4 w4 = *reinterpret_cast<const float4*>(W + idx);
        float acc[4] = {w4.x, w4.y, w4.z, w4.w};
#pragma unroll
        for (int r = 0; r < R_DIM; r++) {
            const float4 a4 =
                *reinterpret_cast<const float4*>(A + (size_t)r * D_DIM + i);
            const float b = bsig[r];
            acc[0] = fmaf(b, a4.x, acc[0]);
            acc[1] = fmaf(b, a4.y, acc[1]);
            acc[2] = fmaf(b, a4.z, acc[2]);
            acc[3] = fmaf(b, a4.w, acc[3]);
        }
        __half h[4];
#pragma unroll
        for (int j = 0; j < 4; j++) h[j] = __float2half_rn(acc[j]);
        *reinterpret_cast<uint2*>(&g_w16[idx]) = *reinterpret_cast<uint2*>(h);
    } else {
        const size_t t = (size_t)(bid >> 1) * 256 + threadIdx.x;
        const float4 v0 = reinterpret_cast<const float4*>(x)[t * 2];
        const float4 v1 = reinterpret_cast<const float4*>(x)[t * 2 + 1];
        __half h[8] = {__float2half_rn(v0.x), __float2half_rn(v0.y),
                       __float2half_rn(v0.z), __float2half_rn(v0.w),
                       __float2half_rn(v1.x), __float2half_rn(v1.y),
                       __float2half_rn(v1.z), __float2half_rn(v1.w)};
        *reinterpret_cast<uint4*>(&g_x16[t * 8]) =
            *reinterpret_cast<uint4*>(h);
    }
}

// ---------------------------------------------------------------------------
// GEMM: CTA 128x128, 256 threads, 8 warps (4m x 2n) of 32x64, BK=64,
// 3-stage pipeline (32 KB/stage) -> 96 KB/CTA -> 2 CTAs/SM, 16 warps/SM.
// (Unchanged — measured at the HMMA issue ceiling.)
// ---------------------------------------------------------------------------
#define STAGE_BYTES 32768
#define OFF_A 0
#define OFF_B 16384
#define SMEM_BYTES (3 * STAGE_BYTES + 128)

__device__ __forceinline__ void load_stage(uint32_t base, size_t mBase,
                                           size_t nBase, int kt, int tid) {
#pragma unroll
    for (int i = 0; i < 4; i++) {   // A: 128 rows x 8 units = 1024 / 256 thr
        const int u = tid + 256 * i;
        const int row = u >> 3, kc = u & 7;
        const uint32_t so = swz128(row * 128 + kc * 16);
        cp16(base + OFF_A + so, g_x16 + ((mBase + row) << 12) + kt + kc * 8);
    }
#pragma unroll
    for (int i = 0; i < 4; i++) {   // B: 128 rows x 8 units
        const int u = tid + 256 * i;
        const int row = u >> 3, kc = u & 7;
        const uint32_t so = swz128(row * 128 + kc * 16);
        cp16(base + OFF_B + so, g_w16 + ((nBase + row) << 12) + kt + kc * 8);
    }
}

__global__ __launch_bounds__(256, 2)
void gemm_mma_kernel(float* __restrict__ out) {
    extern __shared__ char smem_raw[];
    const uint32_t tiles = (smem_u32(smem_raw) + 127u) & ~127u;

    const int tid = threadIdx.x;
    const int lane = tid & 31;
    const int w = tid >> 5;
    const int wm = w >> 1;        // 0..3 -> M quarter (32 rows)
    const int wn = w & 1;         // 0..1 -> N half (64 cols)
    const size_t mBase = (size_t)blockIdx.y * BM;
    const size_t nBase = (size_t)blockIdx.x * BN;

    float d[2][8][4];
#pragma unroll
    for (int i = 0; i < 2; i++)
#pragma unroll
        for (int j = 0; j < 8; j++)
#pragma unroll
            for (int k = 0; k < 4; k++) d[i][j][k] = 0.0f;

    const int arow = wm * 32 + (lane & 15);
    const int acol = (lane >> 4);
    const int brow = wn * 64 + (lane & 7) + ((lane >> 4) << 3);
    const int bcol = ((lane >> 3) & 1);

    load_stage(tiles, mBase, nBase, 0, tid);
    cp_commit();
    load_stage(tiles + STAGE_BYTES, mBase, nBase, BK, tid);
    cp_commit();

    for (int it = 0; it < KITERS; it++) {
        const uint32_t stg = tiles + (it % 3) * STAGE_BYTES;

        cp_wait1();          // oldest pending group (stage it) complete
        __syncthreads();

        // Issue next loads first: stage (it+2)%3 == (it-1)%3 is drained —
        // every warp passed this barrier, so all finished computing it-1.
        if (it + 2 < KITERS)
            load_stage(tiles + ((it + 2) % 3) * STAGE_BYTES,
                       mBase, nBase, (it + 2) * BK, tid);
        cp_commit();         // empty groups at tail keep wait counts valid

#pragma unroll
        for (int k16 = 0; k16 < 4; k16++) {
            uint32_t a[2][4], b[8][2];
#pragma unroll
            for (int mi = 0; mi < 2; mi++) {
                const uint32_t off =
                    swz128((arow + mi * 16) * 128 + (acol + k16 * 2) * 16);
                ldsm4(a[mi], stg + OFF_A + off);
            }
#pragma unroll
            for (int j = 0; j < 4; j++) {
                uint32_t q[4];
                const uint32_t off =
                    swz128((brow + j * 16) * 128 + (bcol + k16 * 2) * 16);
                ldsm4(q, stg + OFF_B + off);
                b[2 * j][0] = q[0]; b[2 * j][1] = q[1];
                b[2 * j + 1][0] = q[2]; b[2 * j + 1][1] = q[3];
            }
#pragma unroll
            for (int mi = 0; mi < 2; mi++)
#pragma unroll
                for (int nj = 0; nj < 8; nj++)
                    mma_f16(d[mi][nj], a[mi], b[nj]);
        }
    }

#pragma unroll
    for (int mi = 0; mi < 2; mi++) {
        const size_t grow = mBase + wm * 32 + mi * 16 + (lane >> 2);
#pragma unroll
        for (int nj = 0; nj < 8; nj++) {
            const size_t gcol = nBase + wn * 64 + nj * 8 + (lane & 3) * 2;
            *reinterpret_cast<float2*>(out + grow * D_DIM + gcol) =
                make_float2(d[mi][nj][0], d[mi][nj][1]);
            *reinterpret_cast<float2*>(out + (grow + 8) * D_DIM + gcol) =
                make_float2(d[mi][nj][2], d[mi][nj][3]);
        }
    }
}

// ---------------------------------------------------------------------------
// Launch
// ---------------------------------------------------------------------------
extern "C" void kernel_launch(void* const* d_in, const int* in_sizes, int n_in,
                              void* d_out, int out_size) {
    const float* x     = (const float*)d_in[0];
    const float* W     = (const float*)d_in[1];
    const float* lA    = (const float*)d_in[2];
    const float* lB    = (const float*)d_in[3];
    const float* sigma = (const float*)d_in[4];
    float* out = (float*)d_out;
    (void)in_sizes; (void)n_in; (void)out_size;

    prep_kernel<<<PREP_BLOCKS, 256>>>(x, W, lA, lB, sigma);

    cudaFuncSetAttribute(gemm_mma_kernel,
                         cudaFuncAttributeMaxDynamicSharedMemorySize, SMEM_BYTES);
    dim3 gG(D_DIM / BN, M_DIM / BM);
    gemm_mma_kernel<<<gG, 256, SMEM_BYTES>>>(out);
}